// round 4
// baseline (speedup 1.0000x reference)
#include <cuda_runtime.h>

typedef unsigned long long u64;

// ---- f32x2 packed helpers (sm_103a) ----------------------------------------
__device__ __forceinline__ u64 pk2(float lo, float hi) {
    u64 r; asm("mov.b64 %0, {%1,%2};" : "=l"(r) : "f"(lo), "f"(hi)); return r;
}
__device__ __forceinline__ void up2(u64 v, float& lo, float& hi) {
    asm("mov.b64 {%0,%1}, %2;" : "=f"(lo), "=f"(hi) : "l"(v));
}
__device__ __forceinline__ u64 addx2(u64 a, u64 b) {
    u64 r; asm("add.rn.f32x2 %0, %1, %2;" : "=l"(r) : "l"(a), "l"(b)); return r;
}
__device__ __forceinline__ u64 mulx2(u64 a, u64 b) {
    u64 r; asm("mul.rn.f32x2 %0, %1, %2;" : "=l"(r) : "l"(a), "l"(b)); return r;
}
__device__ __forceinline__ u64 fmax2p(u64 a, u64 b, u64 c) {
    u64 r; asm("fma.rn.f32x2 %0, %1, %2, %3;" : "=l"(r) : "l"(a), "l"(b), "l"(c)); return r;
}

// ---- scratch (device globals; no allocs allowed) ---------------------------
__device__ float g_A2[1024 * 256];      // a' = x@Wg[:D] + bg
__device__ float g_B2[1024 * 256];      // b  = x@Wg[D:]
__device__ float g_paccv[1024 * 256];   // per (b,ib,jh) partial: sum rs*v_h
__device__ float g_psrm[1024];          // per (b,ib,jh) partial: sum rs*m
__device__ float g_rel[4 * 256];        // final rel vector per batch

// ---------------------------------------------------------------------------
// Kernel A: a' = x @ Wg[:256] + bg ; b = x @ Wg[256:]
// grid (128, 2), block 256. 8 rows x 256 cols per block, FFMA2 over row pairs.
// ---------------------------------------------------------------------------
__global__ __launch_bounds__(256) void gemm_ab(const float* __restrict__ x,
                                               const float* __restrict__ Wg,
                                               const float* __restrict__ bg) {
    int z = blockIdx.y;
    int m0 = blockIdx.x * 8;
    const float* __restrict__ W = Wg + z * 65536;   // Wg[(z*256+d)*256 + h]
    __shared__ float xst[256][12];                  // d-major, 8 rows used
    int tid = threadIdx.x;
#pragma unroll
    for (int r = 0; r < 8; r++) xst[tid][r] = x[(m0 + r) * 256 + tid];
    __syncthreads();

    float bias = (z == 0) ? bg[tid] : 0.0f;
    u64 accp[4];
#pragma unroll
    for (int k = 0; k < 4; k++) accp[k] = pk2(bias, bias);

#pragma unroll 8
    for (int d = 0; d < 256; d++) {
        float w = W[d * 256 + tid];
        u64 wp = pk2(w, w);
        const u64* xr = reinterpret_cast<const u64*>(&xst[d][0]);
#pragma unroll
        for (int k = 0; k < 4; k++) accp[k] = fmax2p(xr[k], wp, accp[k]);
    }

    float* __restrict__ out = z ? g_B2 : g_A2;
#pragma unroll
    for (int k = 0; k < 4; k++) {
        float o0, o1;
        up2(accp[k], o0, o1);
        out[(m0 + 2 * k) * 256 + tid] = o0;
        out[(m0 + 2 * k + 1) * 256 + tid] = o1;
    }
}

// ---------------------------------------------------------------------------
// Kernel B: pair loop. grid (64 ib, 4 b, 4 jh), block 128 (4 warps).
// Warp = 4 groups of 8 lanes. Group g owns row i = ib*4+g (A row kept in
// REGISTERS, ap[16] u64). All groups share the same j each iteration, so the
// B-row loads are warp-broadcast LDG.128s (1 line per instr). Lane s owns
// 32 h at chunks (c*8+s)*4.. LN reduction = 3-step 8-lane butterfly.
// ---------------------------------------------------------------------------
__global__ __launch_bounds__(128) void pair_kernel() {
    int ib = blockIdx.x;
    int b  = blockIdx.y;
    int jh = blockIdx.z;
    int warp = threadIdx.x >> 5;
    int lane = threadIdx.x & 31;
    int g = lane >> 3;     // group -> i row
    int s = lane & 7;      // sublane -> h chunks

    // A row for i = ib*4+g into registers (8 LDG.128, 4x128B segments each)
    const ulonglong2* __restrict__ Ar =
        reinterpret_cast<const ulonglong2*>(g_A2 + (b * 256 + ib * 4 + g) * 256) + s;
    u64 ap[16];
#pragma unroll
    for (int c = 0; c < 8; c++) {
        ulonglong2 t = Ar[c * 8];
        ap[2 * c] = t.x; ap[2 * c + 1] = t.y;
    }

    const ulonglong2* __restrict__ Bb =
        reinterpret_cast<const ulonglong2*>(g_B2 + b * 65536);

    u64 acc[16];
#pragma unroll
    for (int k = 0; k < 16; k++) acc[k] = 0ull;
    float srm = 0.0f;

    int j0 = jh * 64 + warp * 16;
#pragma unroll 2
    for (int t = 0; t < 16; t++) {
        const ulonglong2* __restrict__ Br = Bb + (j0 + t) * 64 + s;
        // pre = a + b, consuming loads directly (broadcast across groups)
        u64 vp[16];
#pragma unroll
        for (int c = 0; c < 8; c++) {
            ulonglong2 u = Br[c * 8];
            vp[2 * c]     = addx2(ap[2 * c], u.x);
            vp[2 * c + 1] = addx2(ap[2 * c + 1], u.y);
        }
        // relu (FMNMX on alu pipe)
#pragma unroll
        for (int k = 0; k < 16; k++) {
            float lo, hi; up2(vp[k], lo, hi);
            vp[k] = pk2(fmaxf(lo, 0.0f), fmaxf(hi, 0.0f));
        }
        // s2 = sum v^2 : 4 parallel chains of 4
        u64 q0 = mulx2(vp[0], vp[0]);
        u64 q1 = mulx2(vp[1], vp[1]);
        u64 q2 = mulx2(vp[2], vp[2]);
        u64 q3 = mulx2(vp[3], vp[3]);
#pragma unroll
        for (int k = 4; k < 16; k += 4) {
            q0 = fmax2p(vp[k],     vp[k],     q0);
            q1 = fmax2p(vp[k + 1], vp[k + 1], q1);
            q2 = fmax2p(vp[k + 2], vp[k + 2], q2);
            q3 = fmax2p(vp[k + 3], vp[k + 3], q3);
        }
        u64 s2p = addx2(addx2(q0, q1), addx2(q2, q3));
        // s1 = sum v : tree
        u64 t0 = addx2(vp[0], vp[1]),   t1 = addx2(vp[2], vp[3]);
        u64 t2 = addx2(vp[4], vp[5]),   t3 = addx2(vp[6], vp[7]);
        u64 t4 = addx2(vp[8], vp[9]),   t5 = addx2(vp[10], vp[11]);
        u64 t6 = addx2(vp[12], vp[13]), t7 = addx2(vp[14], vp[15]);
        t0 = addx2(t0, t1); t2 = addx2(t2, t3);
        t4 = addx2(t4, t5); t6 = addx2(t6, t7);
        u64 s1p = addx2(addx2(t0, t2), addx2(t4, t6));

        float s1a, s1b; up2(s1p, s1a, s1b);
        float s2a, s2b; up2(s2p, s2a, s2b);
        u64 sv = pk2(s1a + s1b, s2a + s2b);
        // 3-step butterfly within the 8-lane group
        sv = addx2(sv, __shfl_xor_sync(0xffffffffu, sv, 1));
        sv = addx2(sv, __shfl_xor_sync(0xffffffffu, sv, 2));
        sv = addx2(sv, __shfl_xor_sync(0xffffffffu, sv, 4));
        float S1, S2; up2(sv, S1, S2);

        float m   = S1 * (1.0f / 256.0f);
        float var = fmaf(S2, 1.0f / 256.0f, -m * m);
        float rs  = rsqrtf(var + 1e-5f);
        u64 rsp = pk2(rs, rs);
#pragma unroll
        for (int k = 0; k < 16; k++) acc[k] = fmax2p(vp[k], rsp, acc[k]);
        srm = fmaf(rs, m, srm);
    }

    // Reduce acc across the 4 groups (sum over i within the warp).
#pragma unroll
    for (int k = 0; k < 16; k++)
        acc[k] = addx2(acc[k], __shfl_xor_sync(0xffffffffu, acc[k], 8));
#pragma unroll
    for (int k = 0; k < 16; k++)
        acc[k] = addx2(acc[k], __shfl_xor_sync(0xffffffffu, acc[k], 16));
    // srm: each group's value replicated on 8 lanes -> full butterfly, /8.
#pragma unroll
    for (int off = 16; off > 0; off >>= 1)
        srm += __shfl_xor_sync(0xffffffffu, srm, off);

    __shared__ float sacc[4][256];
    __shared__ float ssrm[4];
    if (lane < 8) {
        float4* dst = reinterpret_cast<float4*>(&sacc[warp][0]) + lane;
#pragma unroll
        for (int c = 0; c < 8; c++) {
            float a0, a1, a2, a3;
            up2(acc[2 * c], a0, a1);
            up2(acc[2 * c + 1], a2, a3);
            dst[c * 8] = make_float4(a0, a1, a2, a3);   // h = (c*8+lane)*4
        }
        if (lane == 0) ssrm[warp] = srm * 0.125f;
    }
    __syncthreads();

    // 128 threads: each reduces 2 h positions across 4 warps.
    int tid = threadIdx.x;
    int p = (b * 64 + ib) * 4 + jh;
#pragma unroll
    for (int rep = 0; rep < 2; rep++) {
        int h = rep * 128 + tid;
        float tot = sacc[0][h] + sacc[1][h] + sacc[2][h] + sacc[3][h];
        g_paccv[p * 256 + h] = tot;
    }
    if (tid == 0)
        g_psrm[p] = ssrm[0] + ssrm[1] + ssrm[2] + ssrm[3];
}

// ---------------------------------------------------------------------------
// Kernel C: reduce partials -> r_sum, matvec with Wf, relu, LN -> g_rel.
// ---------------------------------------------------------------------------
__global__ __launch_bounds__(256) void finalize(const float* __restrict__ Wf,
                                                const float* __restrict__ bfv,
                                                const float* __restrict__ g_gamma,
                                                const float* __restrict__ g_beta,
                                                const float* __restrict__ f_gamma,
                                                const float* __restrict__ f_beta) {
    int b = blockIdx.x;
    int h = threadIdx.x;
    __shared__ float rsum[256];
    __shared__ float ssr[256];

    float av = 0.0f;
#pragma unroll 8
    for (int p = 0; p < 256; p++) av += g_paccv[(b * 256 + p) * 256 + h];
    ssr[h] = g_psrm[b * 256 + h];
    __syncthreads();

    float srm = 0.0f;
#pragma unroll
    for (int q = 0; q < 256; q++) srm += ssr[q];

    rsum[h] = g_gamma[h] * (av - srm) + 65536.0f * g_beta[h];
    __syncthreads();

    float y = bfv[h];
#pragma unroll 8
    for (int d = 0; d < 256; d++) y = fmaf(rsum[d], Wf[d * 256 + h], y);
    y = fmaxf(y, 0.0f);

    float s1 = y, s2 = y * y;
#pragma unroll
    for (int off = 16; off > 0; off >>= 1) {
        s1 += __shfl_xor_sync(0xffffffffu, s1, off);
        s2 += __shfl_xor_sync(0xffffffffu, s2, off);
    }
    __shared__ float w1[8], w2[8];
    int warp = h >> 5, lane = h & 31;
    if (lane == 0) { w1[warp] = s1; w2[warp] = s2; }
    __syncthreads();
    float S1 = 0.0f, S2 = 0.0f;
#pragma unroll
    for (int w = 0; w < 8; w++) { S1 += w1[w]; S2 += w2[w]; }
    float m = S1 * (1.0f / 256.0f);
    float var = fmaf(S2, 1.0f / 256.0f, -m * m);
    float rs = rsqrtf(var + 1e-5f);
    g_rel[b * 256 + h] = (y - m) * rs * f_gamma[h] + f_beta[h];
}

// ---------------------------------------------------------------------------
// Kernel D: out[b,n,:] = rel[b,:] + x[b,n,:]  (4 independent float4s/thread)
// ---------------------------------------------------------------------------
__global__ __launch_bounds__(128) void add_out(const float* __restrict__ x,
                                               float* __restrict__ out) {
    int base = blockIdx.x * 128 + threadIdx.x;   // 16384 threads
#pragma unroll
    for (int k = 0; k < 4; k++) {
        int i4 = base + k * 16384;               // 0..65535 float4s
        int e  = i4 * 4;
        int b  = e >> 16;
        int d  = e & 255;
        float4 xv = reinterpret_cast<const float4*>(x)[i4];
        float4 rv = *reinterpret_cast<const float4*>(g_rel + b * 256 + d);
        float4 o;
        o.x = xv.x + rv.x;
        o.y = xv.y + rv.y;
        o.z = xv.z + rv.z;
        o.w = xv.w + rv.w;
        reinterpret_cast<float4*>(out)[i4] = o;
    }
}

// ---------------------------------------------------------------------------
extern "C" void kernel_launch(void* const* d_in, const int* in_sizes, int n_in,
                              void* d_out, int out_size) {
    const float* x       = (const float*)d_in[0];
    const float* Wg      = (const float*)d_in[1];
    const float* bg      = (const float*)d_in[2];
    const float* g_gamma = (const float*)d_in[3];
    const float* g_beta  = (const float*)d_in[4];
    const float* Wf      = (const float*)d_in[5];
    const float* bf      = (const float*)d_in[6];
    const float* f_gamma = (const float*)d_in[7];
    const float* f_beta  = (const float*)d_in[8];
    float* out = (float*)d_out;

    gemm_ab<<<dim3(128, 2), 256>>>(x, Wg, bg);
    pair_kernel<<<dim3(64, 4, 4), 128>>>();
    finalize<<<4, 256>>>(Wf, bf, g_gamma, g_beta, f_gamma, f_beta);
    add_out<<<128, 128>>>(x, out);
}

// round 5
// speedup vs baseline: 1.2045x; 1.2045x over previous
#include <cuda_runtime.h>

typedef unsigned long long u64;

// ---- f32x2 packed helpers (sm_103a) ----------------------------------------
__device__ __forceinline__ u64 pk2(float lo, float hi) {
    u64 r; asm("mov.b64 %0, {%1,%2};" : "=l"(r) : "f"(lo), "f"(hi)); return r;
}
__device__ __forceinline__ void up2(u64 v, float& lo, float& hi) {
    asm("mov.b64 {%0,%1}, %2;" : "=f"(lo), "=f"(hi) : "l"(v));
}
__device__ __forceinline__ u64 addx2(u64 a, u64 b) {
    u64 r; asm("add.rn.f32x2 %0, %1, %2;" : "=l"(r) : "l"(a), "l"(b)); return r;
}
__device__ __forceinline__ u64 mulx2(u64 a, u64 b) {
    u64 r; asm("mul.rn.f32x2 %0, %1, %2;" : "=l"(r) : "l"(a), "l"(b)); return r;
}
__device__ __forceinline__ u64 fmax2p(u64 a, u64 b, u64 c) {
    u64 r; asm("fma.rn.f32x2 %0, %1, %2, %3;" : "=l"(r) : "l"(a), "l"(b), "l"(c)); return r;
}

// ---- scratch (device globals; no allocs allowed) ---------------------------
__device__ float g_A2[1024 * 256];     // a' = x@Wg[:D] + bg
__device__ float g_B2[1024 * 256];     // b  = x@Wg[D:]
__device__ float g_paccv[512 * 256];   // per (b*128 + ib*2 + jh): sum rs*v_h
__device__ float g_psrm[512];          // per (b*128 + ib*2 + jh): sum rs*m
__device__ float g_red[32 * 256];      // first-stage reduction of g_paccv
__device__ float g_redm[32];           // first-stage reduction of g_psrm
__device__ float g_rel[4 * 256];       // final rel vector per batch

// ---------------------------------------------------------------------------
// Kernel A: a' = x @ Wg[:256] + bg ; b = x @ Wg[256:]
// grid (128, 2), block 256. 8 rows x 256 cols per block, FFMA2 over row pairs.
// ---------------------------------------------------------------------------
__global__ __launch_bounds__(256) void gemm_ab(const float* __restrict__ x,
                                               const float* __restrict__ Wg,
                                               const float* __restrict__ bg) {
    int z = blockIdx.y;
    int m0 = blockIdx.x * 8;
    const float* __restrict__ W = Wg + z * 65536;   // Wg[(z*256+d)*256 + h]
    __shared__ float xst[256][12];                  // d-major, 8 rows used
    int tid = threadIdx.x;
#pragma unroll
    for (int r = 0; r < 8; r++) xst[tid][r] = x[(m0 + r) * 256 + tid];
    __syncthreads();

    float bias = (z == 0) ? bg[tid] : 0.0f;
    u64 accp[4];
#pragma unroll
    for (int k = 0; k < 4; k++) accp[k] = pk2(bias, bias);

#pragma unroll 8
    for (int d = 0; d < 256; d++) {
        float w = W[d * 256 + tid];
        u64 wp = pk2(w, w);
        const u64* xr = reinterpret_cast<const u64*>(&xst[d][0]);
#pragma unroll
        for (int k = 0; k < 4; k++) accp[k] = fmax2p(xr[k], wp, accp[k]);
    }

    float* __restrict__ out = z ? g_B2 : g_A2;
#pragma unroll
    for (int k = 0; k < 4; k++) {
        float o0, o1;
        up2(accp[k], o0, o1);
        out[(m0 + 2 * k) * 256 + tid] = o0;
        out[(m0 + 2 * k + 1) * 256 + tid] = o1;
    }
}

// ---------------------------------------------------------------------------
// Kernel B: pair loop. grid (64 ib, 4 b, 2 jh), block 256 (8 warps).
// Warp = 2 groups of 16 lanes; group g handles j = j0 + duo*2 + g. Lane s
// owns 16 h at float4 chunks s + c*16 (c=0..3). A tile (4 rows) in smem,
// broadcast LDS. Small live set (~75 regs) -> 3 blocks/SM for latency hiding.
// LN reduction = 4-step 16-lane butterfly shared by 2 groups.
// ---------------------------------------------------------------------------
__global__ __launch_bounds__(256) void pair_kernel() {
    int ib = blockIdx.x;
    int b  = blockIdx.y;
    int jh = blockIdx.z;
    int warp = threadIdx.x >> 5;
    int lane = threadIdx.x & 31;
    int g = lane >> 4;     // group -> j parity
    int s = lane & 15;     // sublane -> h chunks

    __shared__ float sa[4][256];   // 4 A rows for this i-tile
    reinterpret_cast<float4*>(&sa[0][0])[threadIdx.x] =
        reinterpret_cast<const float4*>(g_A2 + (b * 256 + ib * 4) * 256)[threadIdx.x];
    __syncthreads();

    const ulonglong2* __restrict__ Bb =
        reinterpret_cast<const ulonglong2*>(g_B2 + b * 65536);

    u64 acc[8];
#pragma unroll
    for (int k = 0; k < 8; k++) acc[k] = 0ull;
    float srm = 0.0f;

    int j0 = jh * 128 + warp * 16;
#pragma unroll 2
    for (int duo = 0; duo < 8; duo++) {
        int j = j0 + duo * 2 + g;
        const ulonglong2* __restrict__ Br = Bb + j * 64 + s;
        u64 bp[8];
#pragma unroll
        for (int c = 0; c < 4; c++) {
            ulonglong2 t = Br[c * 16];
            bp[2 * c] = t.x; bp[2 * c + 1] = t.y;
        }

#pragma unroll
        for (int ii = 0; ii < 4; ii++) {
            const ulonglong2* Ar =
                reinterpret_cast<const ulonglong2*>(&sa[ii][0]) + s;
            u64 vp[8];
#pragma unroll
            for (int c = 0; c < 4; c++) {
                ulonglong2 t = Ar[c * 16];
                vp[2 * c]     = addx2(t.x, bp[2 * c]);
                vp[2 * c + 1] = addx2(t.y, bp[2 * c + 1]);
            }
            // relu (FMNMX on alu pipe; pack/unpack are register renames)
#pragma unroll
            for (int k = 0; k < 8; k++) {
                float lo, hi; up2(vp[k], lo, hi);
                vp[k] = pk2(fmaxf(lo, 0.0f), fmaxf(hi, 0.0f));
            }
            // s2 = sum v^2 : 2 parallel chains of 4
            u64 q0 = mulx2(vp[0], vp[0]);
            u64 q1 = mulx2(vp[1], vp[1]);
            q0 = fmax2p(vp[2], vp[2], q0);
            q1 = fmax2p(vp[3], vp[3], q1);
            q0 = fmax2p(vp[4], vp[4], q0);
            q1 = fmax2p(vp[5], vp[5], q1);
            q0 = fmax2p(vp[6], vp[6], q0);
            q1 = fmax2p(vp[7], vp[7], q1);
            u64 s2p = addx2(q0, q1);
            // s1 = sum v : tree
            u64 t0 = addx2(vp[0], vp[1]), t1 = addx2(vp[2], vp[3]);
            u64 t2 = addx2(vp[4], vp[5]), t3 = addx2(vp[6], vp[7]);
            u64 s1p = addx2(addx2(t0, t1), addx2(t2, t3));

            float s1a, s1b; up2(s1p, s1a, s1b);
            float s2a, s2b; up2(s2p, s2a, s2b);
            u64 sv = pk2(s1a + s1b, s2a + s2b);
            // 4-step butterfly within the 16-lane group (shared by 2 groups)
            sv = addx2(sv, __shfl_xor_sync(0xffffffffu, sv, 1));
            sv = addx2(sv, __shfl_xor_sync(0xffffffffu, sv, 2));
            sv = addx2(sv, __shfl_xor_sync(0xffffffffu, sv, 4));
            sv = addx2(sv, __shfl_xor_sync(0xffffffffu, sv, 8));
            float S1, S2; up2(sv, S1, S2);

            float m   = S1 * (1.0f / 256.0f);
            float var = fmaf(S2, 1.0f / 256.0f, -m * m);
            float rs  = rsqrtf(var + 1e-5f);
            u64 rsp = pk2(rs, rs);
#pragma unroll
            for (int k = 0; k < 8; k++) acc[k] = fmax2p(vp[k], rsp, acc[k]);
            srm = fmaf(rs, m, srm);
        }
    }

    // Reduce acc across the 2 groups (lanes differing in bit 4).
#pragma unroll
    for (int k = 0; k < 8; k++)
        acc[k] = addx2(acc[k], __shfl_xor_sync(0xffffffffu, acc[k], 16));
    // srm: each group's value replicated on 16 lanes -> full butterfly, /16.
#pragma unroll
    for (int off = 16; off > 0; off >>= 1)
        srm += __shfl_xor_sync(0xffffffffu, srm, off);

    __shared__ float sacc[8][256];
    __shared__ float ssrm[8];
    if (lane < 16) {
        float4* dst = reinterpret_cast<float4*>(&sacc[warp][0]);
#pragma unroll
        for (int c = 0; c < 4; c++) {
            float a0, a1, a2, a3;
            up2(acc[2 * c], a0, a1);
            up2(acc[2 * c + 1], a2, a3);
            dst[s + c * 16] = make_float4(a0, a1, a2, a3);  // h = (s+c*16)*4
        }
        if (lane == 0) ssrm[warp] = srm * 0.0625f;
    }
    __syncthreads();

    int tid = threadIdx.x;
    float tot = 0.0f;
#pragma unroll
    for (int w = 0; w < 8; w++) tot += sacc[w][tid];
    int p = b * 128 + ib * 2 + jh;
    g_paccv[p * 256 + tid] = tot;
    if (tid == 0) {
        float sm = 0.0f;
#pragma unroll
        for (int w = 0; w < 8; w++) sm += ssrm[w];
        g_psrm[p] = sm;
    }
}

// ---------------------------------------------------------------------------
// Kernel B2: first-stage reduction. grid 32 (4 b x 8), block 256.
// Block k sums 16 partial rows -> g_red[k], and the psrm scalars.
// ---------------------------------------------------------------------------
__global__ __launch_bounds__(256) void reduce1() {
    int k = blockIdx.x;        // 0..31
    int b = k >> 3, r = k & 7;
    int h = threadIdx.x;
    int p0 = b * 128 + r * 16;
    float sum = 0.0f;
#pragma unroll
    for (int q = 0; q < 16; q++) sum += g_paccv[(p0 + q) * 256 + h];
    g_red[k * 256 + h] = sum;

    __shared__ float sm[16];
    if (h < 16) sm[h] = g_psrm[p0 + h];
    __syncthreads();
    if (h == 0) {
        float t = 0.0f;
#pragma unroll
        for (int q = 0; q < 16; q++) t += sm[q];
        g_redm[k] = t;
    }
}

// ---------------------------------------------------------------------------
// Kernel C: reduce stage-1 partials -> r_sum, matvec Wf, relu, LN -> g_rel.
// ---------------------------------------------------------------------------
__global__ __launch_bounds__(256) void finalize(const float* __restrict__ Wf,
                                                const float* __restrict__ bfv,
                                                const float* __restrict__ g_gamma,
                                                const float* __restrict__ g_beta,
                                                const float* __restrict__ f_gamma,
                                                const float* __restrict__ f_beta) {
    int b = blockIdx.x;
    int h = threadIdx.x;
    __shared__ float rsum[256];

    float av = 0.0f;
#pragma unroll
    for (int r = 0; r < 8; r++) av += g_red[(b * 8 + r) * 256 + h];
    float srm = 0.0f;
#pragma unroll
    for (int r = 0; r < 8; r++) srm += g_redm[b * 8 + r];

    rsum[h] = g_gamma[h] * (av - srm) + 65536.0f * g_beta[h];
    __syncthreads();

    float y = bfv[h];
#pragma unroll 8
    for (int d = 0; d < 256; d++) y = fmaf(rsum[d], Wf[d * 256 + h], y);
    y = fmaxf(y, 0.0f);

    float s1 = y, s2 = y * y;
#pragma unroll
    for (int off = 16; off > 0; off >>= 1) {
        s1 += __shfl_xor_sync(0xffffffffu, s1, off);
        s2 += __shfl_xor_sync(0xffffffffu, s2, off);
    }
    __shared__ float w1[8], w2[8];
    int warp = h >> 5, lane = h & 31;
    if (lane == 0) { w1[warp] = s1; w2[warp] = s2; }
    __syncthreads();
    float S1 = 0.0f, S2 = 0.0f;
#pragma unroll
    for (int w = 0; w < 8; w++) { S1 += w1[w]; S2 += w2[w]; }
    float m = S1 * (1.0f / 256.0f);
    float var = fmaf(S2, 1.0f / 256.0f, -m * m);
    float rs = rsqrtf(var + 1e-5f);
    g_rel[b * 256 + h] = (y - m) * rs * f_gamma[h] + f_beta[h];
}

// ---------------------------------------------------------------------------
// Kernel D: out[b,n,:] = rel[b,:] + x[b,n,:]  (1 float4 per thread, 65536 thr)
// ---------------------------------------------------------------------------
__global__ __launch_bounds__(256) void add_out(const float* __restrict__ x,
                                               float* __restrict__ out) {
    int i4 = blockIdx.x * 256 + threadIdx.x;  // 0..65535 float4s
    int e  = i4 * 4;
    int b  = e >> 16;
    int d  = e & 255;
    float4 xv = reinterpret_cast<const float4*>(x)[i4];
    float4 rv = *reinterpret_cast<const float4*>(g_rel + b * 256 + d);
    float4 o;
    o.x = xv.x + rv.x;
    o.y = xv.y + rv.y;
    o.z = xv.z + rv.z;
    o.w = xv.w + rv.w;
    reinterpret_cast<float4*>(out)[i4] = o;
}

// ---------------------------------------------------------------------------
extern "C" void kernel_launch(void* const* d_in, const int* in_sizes, int n_in,
                              void* d_out, int out_size) {
    const float* x       = (const float*)d_in[0];
    const float* Wg      = (const float*)d_in[1];
    const float* bg      = (const float*)d_in[2];
    const float* g_gamma = (const float*)d_in[3];
    const float* g_beta  = (const float*)d_in[4];
    const float* Wf      = (const float*)d_in[5];
    const float* bf      = (const float*)d_in[6];
    const float* f_gamma = (const float*)d_in[7];
    const float* f_beta  = (const float*)d_in[8];
    float* out = (float*)d_out;

    gemm_ab<<<dim3(128, 2), 256>>>(x, Wg, bg);
    pair_kernel<<<dim3(64, 4, 2), 256>>>();
    reduce1<<<32, 256>>>();
    finalize<<<4, 256>>>(Wf, bf, g_gamma, g_beta, f_gamma, f_beta);
    add_out<<<256, 256>>>(x, out);
}

// round 6
// speedup vs baseline: 1.3585x; 1.1279x over previous
#include <cuda_runtime.h>

typedef unsigned long long u64;

// ---- f32x2 packed helpers (sm_103a) ----------------------------------------
__device__ __forceinline__ u64 pk2(float lo, float hi) {
    u64 r; asm("mov.b64 %0, {%1,%2};" : "=l"(r) : "f"(lo), "f"(hi)); return r;
}
__device__ __forceinline__ void up2(u64 v, float& lo, float& hi) {
    asm("mov.b64 {%0,%1}, %2;" : "=f"(lo), "=f"(hi) : "l"(v));
}
__device__ __forceinline__ u64 addx2(u64 a, u64 b) {
    u64 r; asm("add.rn.f32x2 %0, %1, %2;" : "=l"(r) : "l"(a), "l"(b)); return r;
}
__device__ __forceinline__ u64 mulx2(u64 a, u64 b) {
    u64 r; asm("mul.rn.f32x2 %0, %1, %2;" : "=l"(r) : "l"(a), "l"(b)); return r;
}
__device__ __forceinline__ u64 fmax2p(u64 a, u64 b, u64 c) {
    u64 r; asm("fma.rn.f32x2 %0, %1, %2, %3;" : "=l"(r) : "l"(a), "l"(b), "l"(c)); return r;
}

// ---- scratch (device globals; no allocs allowed) ---------------------------
__device__ float g_A2[1024 * 256];     // a' = x@Wg[:D] + bg
__device__ float g_B2[1024 * 256];     // b  = x@Wg[D:]
__device__ float g_paccv[512 * 256];   // per (b*128 + ib*2 + jh): sum rs*v_h
__device__ float g_psrm[512];          // per (b*128 + ib*2 + jh): sum rs*m
__device__ float g_red[32 * 256];      // first-stage reduction of g_paccv
__device__ float g_redm[32];           // first-stage reduction of g_psrm
__device__ float g_ypart[64 * 256];    // matvec partials per (b, d-slice)
__device__ float g_rel[4 * 256];       // final rel vector per batch

// ---------------------------------------------------------------------------
// Kernel A: a' = x @ Wg[:256] + bg ; b = x @ Wg[256:]
// ---------------------------------------------------------------------------
__global__ __launch_bounds__(256) void gemm_ab(const float* __restrict__ x,
                                               const float* __restrict__ Wg,
                                               const float* __restrict__ bg) {
    int z = blockIdx.y;
    int m0 = blockIdx.x * 8;
    const float* __restrict__ W = Wg + z * 65536;   // Wg[(z*256+d)*256 + h]
    __shared__ float xst[256][12];                  // d-major, 8 rows used
    int tid = threadIdx.x;
#pragma unroll
    for (int r = 0; r < 8; r++) xst[tid][r] = x[(m0 + r) * 256 + tid];
    __syncthreads();

    float bias = (z == 0) ? bg[tid] : 0.0f;
    u64 accp[4];
#pragma unroll
    for (int k = 0; k < 4; k++) accp[k] = pk2(bias, bias);

#pragma unroll 8
    for (int d = 0; d < 256; d++) {
        float w = W[d * 256 + tid];
        u64 wp = pk2(w, w);
        const u64* xr = reinterpret_cast<const u64*>(&xst[d][0]);
#pragma unroll
        for (int k = 0; k < 4; k++) accp[k] = fmax2p(xr[k], wp, accp[k]);
    }

    float* __restrict__ out = z ? g_B2 : g_A2;
#pragma unroll
    for (int k = 0; k < 4; k++) {
        float o0, o1;
        up2(accp[k], o0, o1);
        out[(m0 + 2 * k) * 256 + tid] = o0;
        out[(m0 + 2 * k + 1) * 256 + tid] = o1;
    }
}

// ---------------------------------------------------------------------------
// Kernel B: pair loop. grid (64 ib, 4 b, 2 jh), block 256 (8 warps).
// Warp = 2 groups of 16 lanes; group g handles j = j0 + duo*2 + g. Lane s
// owns 16 h at float4 chunks s + c*16. A tile in smem (broadcast LDS).
// ---------------------------------------------------------------------------
__global__ __launch_bounds__(256) void pair_kernel() {
    int ib = blockIdx.x;
    int b  = blockIdx.y;
    int jh = blockIdx.z;
    int warp = threadIdx.x >> 5;
    int lane = threadIdx.x & 31;
    int g = lane >> 4;     // group -> j parity
    int s = lane & 15;     // sublane -> h chunks

    __shared__ float sa[4][256];   // 4 A rows for this i-tile
    reinterpret_cast<float4*>(&sa[0][0])[threadIdx.x] =
        reinterpret_cast<const float4*>(g_A2 + (b * 256 + ib * 4) * 256)[threadIdx.x];
    __syncthreads();

    const ulonglong2* __restrict__ Bb =
        reinterpret_cast<const ulonglong2*>(g_B2 + b * 65536);

    u64 acc[8];
#pragma unroll
    for (int k = 0; k < 8; k++) acc[k] = 0ull;
    float srm = 0.0f;

    int j0 = jh * 128 + warp * 16;
#pragma unroll 2
    for (int duo = 0; duo < 8; duo++) {
        int j = j0 + duo * 2 + g;
        const ulonglong2* __restrict__ Br = Bb + j * 64 + s;
        u64 bp[8];
#pragma unroll
        for (int c = 0; c < 4; c++) {
            ulonglong2 t = Br[c * 16];
            bp[2 * c] = t.x; bp[2 * c + 1] = t.y;
        }

#pragma unroll
        for (int ii = 0; ii < 4; ii++) {
            const ulonglong2* Ar =
                reinterpret_cast<const ulonglong2*>(&sa[ii][0]) + s;
            u64 vp[8];
#pragma unroll
            for (int c = 0; c < 4; c++) {
                ulonglong2 t = Ar[c * 16];
                vp[2 * c]     = addx2(t.x, bp[2 * c]);
                vp[2 * c + 1] = addx2(t.y, bp[2 * c + 1]);
            }
#pragma unroll
            for (int k = 0; k < 8; k++) {
                float lo, hi; up2(vp[k], lo, hi);
                vp[k] = pk2(fmaxf(lo, 0.0f), fmaxf(hi, 0.0f));
            }
            u64 q0 = mulx2(vp[0], vp[0]);
            u64 q1 = mulx2(vp[1], vp[1]);
            q0 = fmax2p(vp[2], vp[2], q0);
            q1 = fmax2p(vp[3], vp[3], q1);
            q0 = fmax2p(vp[4], vp[4], q0);
            q1 = fmax2p(vp[5], vp[5], q1);
            q0 = fmax2p(vp[6], vp[6], q0);
            q1 = fmax2p(vp[7], vp[7], q1);
            u64 s2p = addx2(q0, q1);
            u64 t0 = addx2(vp[0], vp[1]), t1 = addx2(vp[2], vp[3]);
            u64 t2 = addx2(vp[4], vp[5]), t3 = addx2(vp[6], vp[7]);
            u64 s1p = addx2(addx2(t0, t1), addx2(t2, t3));

            float s1a, s1b; up2(s1p, s1a, s1b);
            float s2a, s2b; up2(s2p, s2a, s2b);
            u64 sv = pk2(s1a + s1b, s2a + s2b);
            sv = addx2(sv, __shfl_xor_sync(0xffffffffu, sv, 1));
            sv = addx2(sv, __shfl_xor_sync(0xffffffffu, sv, 2));
            sv = addx2(sv, __shfl_xor_sync(0xffffffffu, sv, 4));
            sv = addx2(sv, __shfl_xor_sync(0xffffffffu, sv, 8));
            float S1, S2; up2(sv, S1, S2);

            float m   = S1 * (1.0f / 256.0f);
            float var = fmaf(S2, 1.0f / 256.0f, -m * m);
            float rs  = rsqrtf(var + 1e-5f);
            u64 rsp = pk2(rs, rs);
#pragma unroll
            for (int k = 0; k < 8; k++) acc[k] = fmax2p(vp[k], rsp, acc[k]);
            srm = fmaf(rs, m, srm);
        }
    }

#pragma unroll
    for (int k = 0; k < 8; k++)
        acc[k] = addx2(acc[k], __shfl_xor_sync(0xffffffffu, acc[k], 16));
#pragma unroll
    for (int off = 16; off > 0; off >>= 1)
        srm += __shfl_xor_sync(0xffffffffu, srm, off);

    __shared__ float sacc[8][256];
    __shared__ float ssrm[8];
    if (lane < 16) {
        float4* dst = reinterpret_cast<float4*>(&sacc[warp][0]);
#pragma unroll
        for (int c = 0; c < 4; c++) {
            float a0, a1, a2, a3;
            up2(acc[2 * c], a0, a1);
            up2(acc[2 * c + 1], a2, a3);
            dst[s + c * 16] = make_float4(a0, a1, a2, a3);  // h = (s+c*16)*4
        }
        if (lane == 0) ssrm[warp] = srm * 0.0625f;
    }
    __syncthreads();

    int tid = threadIdx.x;
    float tot = 0.0f;
#pragma unroll
    for (int w = 0; w < 8; w++) tot += sacc[w][tid];
    int p = b * 128 + ib * 2 + jh;
    g_paccv[p * 256 + tid] = tot;
    if (tid == 0) {
        float sm = 0.0f;
#pragma unroll
        for (int w = 0; w < 8; w++) sm += ssrm[w];
        g_psrm[p] = sm;
    }
}

// ---------------------------------------------------------------------------
// Kernel B2: first-stage reduction. grid 32 (4 b x 8), block 256.
// ---------------------------------------------------------------------------
__global__ __launch_bounds__(256) void reduce1() {
    int k = blockIdx.x;        // 0..31
    int b = k >> 3, r = k & 7;
    int h = threadIdx.x;
    int p0 = b * 128 + r * 16;
    float sum = 0.0f;
#pragma unroll
    for (int q = 0; q < 16; q++) sum += g_paccv[(p0 + q) * 256 + h];
    g_red[k * 256 + h] = sum;

    __shared__ float sm[16];
    if (h < 16) sm[h] = g_psrm[p0 + h];
    __syncthreads();
    if (h == 0) {
        float t = 0.0f;
#pragma unroll
        for (int q = 0; q < 16; q++) t += sm[q];
        g_redm[k] = t;
    }
}

// ---------------------------------------------------------------------------
// Kernel C1: matvec partials. grid (16 slices, 4 b), block 256.
// Block (r,b): rsum[d] for d in [r*16, r*16+16) from g_red (L2-hot), then
// y_part[h] = sum_{k<16} rsum[r*16+k] * Wf[(r*16+k)*256 + h].
// ---------------------------------------------------------------------------
__global__ __launch_bounds__(256) void matvec(const float* __restrict__ Wf,
                                              const float* __restrict__ g_gamma,
                                              const float* __restrict__ g_beta) {
    int r = blockIdx.x;
    int b = blockIdx.y;
    int t = threadIdx.x;
    __shared__ float rs[16];
    if (t < 16) {
        int d = r * 16 + t;
        float av = 0.0f, sm = 0.0f;
#pragma unroll
        for (int q = 0; q < 8; q++) {
            av += g_red[(b * 8 + q) * 256 + d];
            sm += g_redm[b * 8 + q];
        }
        rs[t] = g_gamma[d] * (av - sm) + 65536.0f * g_beta[d];
    }
    __syncthreads();

    const float* __restrict__ Wr = Wf + (r * 16) * 256 + t;
    float y = 0.0f;
#pragma unroll
    for (int k = 0; k < 16; k++) y = fmaf(rs[k], Wr[k * 256], y);
    g_ypart[(b * 16 + r) * 256 + t] = y;
}

// ---------------------------------------------------------------------------
// Kernel C2: y = relu(bf + sum partials), LayerNorm -> g_rel. grid 4.
// ---------------------------------------------------------------------------
__global__ __launch_bounds__(256) void ln_final(const float* __restrict__ bfv,
                                                const float* __restrict__ f_gamma,
                                                const float* __restrict__ f_beta) {
    int b = blockIdx.x;
    int h = threadIdx.x;

    float y = bfv[h];
#pragma unroll
    for (int r = 0; r < 16; r++) y += g_ypart[(b * 16 + r) * 256 + h];
    y = fmaxf(y, 0.0f);

    float s1 = y, s2 = y * y;
#pragma unroll
    for (int off = 16; off > 0; off >>= 1) {
        s1 += __shfl_xor_sync(0xffffffffu, s1, off);
        s2 += __shfl_xor_sync(0xffffffffu, s2, off);
    }
    __shared__ float w1[8], w2[8];
    int warp = h >> 5, lane = h & 31;
    if (lane == 0) { w1[warp] = s1; w2[warp] = s2; }
    __syncthreads();
    float S1 = 0.0f, S2 = 0.0f;
#pragma unroll
    for (int w = 0; w < 8; w++) { S1 += w1[w]; S2 += w2[w]; }
    float m = S1 * (1.0f / 256.0f);
    float var = fmaf(S2, 1.0f / 256.0f, -m * m);
    float rsq = rsqrtf(var + 1e-5f);
    g_rel[b * 256 + h] = (y - m) * rsq * f_gamma[h] + f_beta[h];
}

// ---------------------------------------------------------------------------
// Kernel D: out[b,n,:] = rel[b,:] + x[b,n,:]
// ---------------------------------------------------------------------------
__global__ __launch_bounds__(256) void add_out(const float* __restrict__ x,
                                               float* __restrict__ out) {
    int i4 = blockIdx.x * 256 + threadIdx.x;  // 0..65535 float4s
    int e  = i4 * 4;
    int b  = e >> 16;
    int d  = e & 255;
    float4 xv = reinterpret_cast<const float4*>(x)[i4];
    float4 rv = *reinterpret_cast<const float4*>(g_rel + b * 256 + d);
    float4 o;
    o.x = xv.x + rv.x;
    o.y = xv.y + rv.y;
    o.z = xv.z + rv.z;
    o.w = xv.w + rv.w;
    reinterpret_cast<float4*>(out)[i4] = o;
}

// ---------------------------------------------------------------------------
extern "C" void kernel_launch(void* const* d_in, const int* in_sizes, int n_in,
                              void* d_out, int out_size) {
    const float* x       = (const float*)d_in[0];
    const float* Wg      = (const float*)d_in[1];
    const float* bg      = (const float*)d_in[2];
    const float* g_gamma = (const float*)d_in[3];
    const float* g_beta  = (const float*)d_in[4];
    const float* Wf      = (const float*)d_in[5];
    const float* bf      = (const float*)d_in[6];
    const float* f_gamma = (const float*)d_in[7];
    const float* f_beta  = (const float*)d_in[8];
    float* out = (float*)d_out;

    gemm_ab<<<dim3(128, 2), 256>>>(x, Wg, bg);
    pair_kernel<<<dim3(64, 4, 2), 256>>>();
    reduce1<<<32, 256>>>();
    matvec<<<dim3(16, 4), 256>>>(Wf, g_gamma, g_beta);
    ln_final<<<4, 256>>>(bf, f_gamma, f_beta);
    add_out<<<256, 256>>>(x, out);
}